// round 1
// baseline (speedup 1.0000x reference)
#include <cuda_runtime.h>

// BoidPolicy: all-pairs boids steering on a unit torus.
// N = 8192, output acc [N,2] float32.
//
// Inputs (metadata order):
//   d_in[0] position [N,2] f32
//   d_in[1] velocity [N,2] f32
//   d_in[2] noise    [N,2] f32
//   d_in[3] separation_weight (1) f32
//   d_in[4] alignment_weight  (1) f32
//   d_in[5] cohesion_weight   (1) f32
//   d_in[6] noise_scale       (1) f32

#define N_BOIDS   8192
#define SEP2      (0.02f * 0.02f)   // 4e-4
#define PERC2     (0.2f * 0.2f)     // 0.04
#define EPSF      1e-8f

// Block layout: 32 i-lanes x 8 j-segments = 256 threads.
// Each thread: one boid i, one 1024-long slice of j.
#define IPB    32     // boids (i) per block
#define SEGS   8      // j segments per block (= warps per block)
#define SEGLEN (N_BOIDS / SEGS)   // 1024

__global__ __launch_bounds__(IPB * SEGS)
void boids_kernel(const float2* __restrict__ pos,
                  const float2* __restrict__ vel,
                  const float2* __restrict__ noise,
                  const float*  __restrict__ w_sep,
                  const float*  __restrict__ w_ali,
                  const float*  __restrict__ w_coh,
                  const float*  __restrict__ w_ns,
                  float2*       __restrict__ out)
{
    // [seg][i_lane][component], component padded 7->8
    __shared__ float red[SEGS][IPB][8];

    const int lane = threadIdx.x & 31;   // i within block (warp lane)
    const int seg  = threadIdx.x >> 5;   // j segment (warp id)
    const int i    = (blockIdx.x << 5) + lane;

    const float2 pi = pos[i];
    const float pix = pi.x;
    const float piy = pi.y;

    float sx = 0.0f, sy = 0.0f;   // sum of toroidal diff over separation mask
    float vx = 0.0f, vy = 0.0f;   // sum of neighbor velocity over perception mask (incl self)
    float px = 0.0f, py = 0.0f;   // sum of toroidal diff over perception mask
    int   cnt = 0;                // perception count (incl self)

    const int j0 = seg * SEGLEN;

    #pragma unroll 4
    for (int jj = 0; jj < SEGLEN; ++jj) {
        const int j = j0 + jj;
        const float2 pj = pos[j];   // warp-uniform -> broadcast, L1 resident (128 KB total)
        const float2 vj = vel[j];

        float dx = pj.x - pix;
        float dy = pj.y - piy;
        // toroidal wrap: |dx| < 1 so wrap correction is exactly -rint(dx) in {-1,0,1};
        // ties (|dx|==0.5) round to even -> 0, matching the reference's strict > / <.
        dx -= rintf(dx);
        dy -= rintf(dy);

        const float d2 = fmaf(dy, dy, dx * dx);

        if (d2 <= SEP2) {          // self: dx=dy=0 -> harmless
            sx += dx;
            sy += dy;
        }
        if (d2 <= PERC2) {         // self included; corrected in epilogue
            cnt += 1;
            vx += vj.x;
            vy += vj.y;
            px += dx;
            py += dy;
        }
    }

    red[seg][lane][0] = sx;
    red[seg][lane][1] = sy;
    red[seg][lane][2] = vx;
    red[seg][lane][3] = vy;
    red[seg][lane][4] = px;
    red[seg][lane][5] = py;
    red[seg][lane][6] = (float)cnt;
    __syncthreads();

    // Deterministic cross-segment reduction: one thread per (i_lane, component).
    for (int idx = threadIdx.x; idx < IPB * 7; idx += IPB * SEGS) {
        const int l = idx / 7;
        const int c = idx % 7;
        float s = 0.0f;
        #pragma unroll
        for (int sg = 0; sg < SEGS; ++sg) s += red[sg][l][c];
        red[0][l][c] = s;   // only this thread touches [l][c]
    }
    __syncthreads();

    // Finalize: one thread per boid in this block.
    if (threadIdx.x < IPB) {
        const int l  = threadIdx.x;
        const int ib = (blockIdx.x << 5) + l;

        const float Sx = red[0][l][0];
        const float Sy = red[0][l][1];
        const float Vx = red[0][l][2];
        const float Vy = red[0][l][3];
        const float Px = red[0][l][4];
        const float Py = red[0][l][5];
        const float C  = red[0][l][6] - 1.0f;   // remove self

        const float2 vi = vel[ib];
        const float2 nz = noise[ib];

        // separation: normalize(-S)
        float nrm = sqrtf(Sx * Sx + Sy * Sy);
        float inv = 1.0f / fmaxf(nrm, EPSF);
        const float sepx = -Sx * inv;
        const float sepy = -Sy * inv;

        const float invC = 1.0f / C;

        // alignment: normalize( (V - vi)/C - vi )
        const float avx = (Vx - vi.x) * invC - vi.x;
        const float avy = (Vy - vi.y) * invC - vi.y;
        nrm = sqrtf(avx * avx + avy * avy);
        inv = 1.0f / fmaxf(nrm, EPSF);
        const float alix = avx * inv;
        const float aliy = avy * inv;

        // cohesion: normalize( P/C )
        const float cx = Px * invC;
        const float cy = Py * invC;
        nrm = sqrtf(cx * cx + cy * cy);
        inv = 1.0f / fmaxf(nrm, EPSF);
        const float cohx = cx * inv;
        const float cohy = cy * inv;

        const float ws = *w_sep;
        const float wa = *w_ali;
        const float wc = *w_coh;
        const float wn = *w_ns;

        float ax = ws * sepx + wa * alix + wc * cohx + wn * nz.x;
        float ay = ws * sepy + wa * aliy + wc * cohy + wn * nz.y;

        // clip by norm to ACC_MAX = 1
        nrm = sqrtf(ax * ax + ay * ay);
        if (nrm > 1.0f) {
            const float s = 1.0f / fmaxf(nrm, EPSF);
            ax *= s;
            ay *= s;
        }

        out[ib] = make_float2(ax, ay);
    }
}

extern "C" void kernel_launch(void* const* d_in, const int* in_sizes, int n_in,
                              void* d_out, int out_size)
{
    const float2* pos   = (const float2*)d_in[0];
    const float2* vel   = (const float2*)d_in[1];
    const float2* noise = (const float2*)d_in[2];
    const float*  wsep  = (const float*)d_in[3];
    const float*  wali  = (const float*)d_in[4];
    const float*  wcoh  = (const float*)d_in[5];
    const float*  wns   = (const float*)d_in[6];
    float2* out = (float2*)d_out;

    boids_kernel<<<N_BOIDS / IPB, IPB * SEGS>>>(pos, vel, noise,
                                                wsep, wali, wcoh, wns, out);
}

// round 2
// speedup vs baseline: 1.3701x; 1.3701x over previous
#include <cuda_runtime.h>

// BoidPolicy: all-pairs boids steering on a unit torus. N=8192, out acc [N,2] f32.
//
// Decomposition: grid = 512 blocks x 256 threads.
//   Each block handles IBLK=16 boids (i) against all 8192 j.
//   Thread t: l = t&7 (i-lane), sg = (t>>3)&3 (sub-segment), w = t>>5 (warp).
//   Thread owns i0 = base+l and i1 = base+l+8 (IPT=2), and j-slice
//   { w*1024 + jj*4 + sg : jj in [0,256) }  -> warp's 4 sub-segments read
//   4 CONSECUTIVE j per LDG (one 32B sector).
//   32 partial sums per i reduced through shared memory, epilogue in-block.

#define NB      8192
#define L_I     8
#define IPT     2
#define IBLK    (L_I * IPT)        // 16
#define TPB     256
#define GRID    (NB / IBLK)        // 512
#define JW      1024               // j-range per warp
#define ITERS   (JW / 4)           // 256
#define SGS     32                 // partial-sum slots (8 warps x 4 subsegs)

#define SEP2F   4e-4f              // 0.02^2
#define PERC2F  0.04f              // 0.2^2
#define EPSF    1e-8f

__global__ __launch_bounds__(TPB)
void boids_kernel(const float2* __restrict__ pos,
                  const float2* __restrict__ vel,
                  const float2* __restrict__ noise,
                  const float*  __restrict__ w_sep,
                  const float*  __restrict__ w_ali,
                  const float*  __restrict__ w_coh,
                  const float*  __restrict__ w_ns,
                  float2*       __restrict__ out)
{
    __shared__ float red[SGS][IBLK][8];   // [seg][i][7 comps, padded]

    const int tid = threadIdx.x;
    const int l   = tid & 7;
    const int sg  = (tid >> 3) & 3;
    const int w   = tid >> 5;
    const int seg = tid >> 3;             // 0..31
    const int i0  = blockIdx.x * IBLK + l;
    const int i1  = i0 + L_I;

    const float2 p0 = pos[i0];
    const float2 p1 = pos[i1];

    // packed (x,y) accumulators: S = sep diff sum, V = vel sum, P = perc diff sum
    unsigned long long S0 = 0ull, V0 = 0ull, P0 = 0ull;
    unsigned long long S1 = 0ull, V1 = 0ull, P1 = 0ull;
    float c0 = 0.0f, c1 = 0.0f;

    const float sep2  = SEP2F;
    const float perc2 = PERC2F;

    const float2* __restrict__ pp =
        pos + (size_t)w * JW + sg;
    const unsigned long long* __restrict__ vv =
        (const unsigned long long*)vel + (size_t)w * JW + sg;

    #pragma unroll 4
    for (int jj = 0; jj < ITERS; ++jj) {
        const float2 pj = pp[jj * 4];
        const unsigned long long vj = vv[jj * 4];

        // ---- i0 ----
        {
            float dx = pj.x - p0.x;
            float dy = pj.y - p0.y;
            // wrapped |d| = 0.5 - |0.5 - |d||   (abs = free operand modifier)
            float tx = 0.5f - fabsf(dx);
            float ty = 0.5f - fabsf(dy);
            float ax = 0.5f - fabsf(tx);
            float ay = 0.5f - fabsf(ty);
            float d2 = fmaf(ay, ay, ax * ax);
            // sign(dw) = sign(dx * (0.5 - |dx|))
            float dwx = copysignf(ax, dx * tx);
            float dwy = copysignf(ay, dy * ty);
            unsigned long long dw;
            asm("mov.b64 %0, {%1, %2};" : "=l"(dw) : "f"(dwx), "f"(dwy));
            asm("{\n\t"
                ".reg .pred q1, q2;\n\t"
                "setp.le.f32 q1, %4, %6;\n\t"
                "setp.le.f32 q2, %4, %7;\n\t"
                "@q1 add.rn.f32x2 %0, %0, %5;\n\t"
                "@q2 add.rn.f32x2 %1, %1, %8;\n\t"
                "@q2 add.rn.f32x2 %2, %2, %5;\n\t"
                "@q2 add.f32 %3, %3, 0f3F800000;\n\t"
                "}"
                : "+l"(S0), "+l"(V0), "+l"(P0), "+f"(c0)
                : "f"(d2), "l"(dw), "f"(sep2), "f"(perc2), "l"(vj));
        }
        // ---- i1 ----
        {
            float dx = pj.x - p1.x;
            float dy = pj.y - p1.y;
            float tx = 0.5f - fabsf(dx);
            float ty = 0.5f - fabsf(dy);
            float ax = 0.5f - fabsf(tx);
            float ay = 0.5f - fabsf(ty);
            float d2 = fmaf(ay, ay, ax * ax);
            float dwx = copysignf(ax, dx * tx);
            float dwy = copysignf(ay, dy * ty);
            unsigned long long dw;
            asm("mov.b64 %0, {%1, %2};" : "=l"(dw) : "f"(dwx), "f"(dwy));
            asm("{\n\t"
                ".reg .pred q1, q2;\n\t"
                "setp.le.f32 q1, %4, %6;\n\t"
                "setp.le.f32 q2, %4, %7;\n\t"
                "@q1 add.rn.f32x2 %0, %0, %5;\n\t"
                "@q2 add.rn.f32x2 %1, %1, %8;\n\t"
                "@q2 add.rn.f32x2 %2, %2, %5;\n\t"
                "@q2 add.f32 %3, %3, 0f3F800000;\n\t"
                "}"
                : "+l"(S1), "+l"(V1), "+l"(P1), "+f"(c1)
                : "f"(d2), "l"(dw), "f"(sep2), "f"(perc2), "l"(vj));
        }
    }

    // unpack + store partials
    {
        float x, y;
        asm("mov.b64 {%0,%1}, %2;" : "=f"(x), "=f"(y) : "l"(S0));
        red[seg][l][0] = x;  red[seg][l][1] = y;
        asm("mov.b64 {%0,%1}, %2;" : "=f"(x), "=f"(y) : "l"(V0));
        red[seg][l][2] = x;  red[seg][l][3] = y;
        asm("mov.b64 {%0,%1}, %2;" : "=f"(x), "=f"(y) : "l"(P0));
        red[seg][l][4] = x;  red[seg][l][5] = y;
        red[seg][l][6] = c0;

        asm("mov.b64 {%0,%1}, %2;" : "=f"(x), "=f"(y) : "l"(S1));
        red[seg][l + L_I][0] = x;  red[seg][l + L_I][1] = y;
        asm("mov.b64 {%0,%1}, %2;" : "=f"(x), "=f"(y) : "l"(V1));
        red[seg][l + L_I][2] = x;  red[seg][l + L_I][3] = y;
        asm("mov.b64 {%0,%1}, %2;" : "=f"(x), "=f"(y) : "l"(P1));
        red[seg][l + L_I][4] = x;  red[seg][l + L_I][5] = y;
        red[seg][l + L_I][6] = c1;
    }
    __syncthreads();

    // deterministic cross-segment reduction: one thread per (i, comp)
    for (int idx = tid; idx < IBLK * 7; idx += TPB) {
        const int li = idx / 7;
        const int c  = idx % 7;
        float s = 0.0f;
        #pragma unroll
        for (int sgi = 0; sgi < SGS; ++sgi) s += red[sgi][li][c];
        red[0][li][c] = s;
    }
    __syncthreads();

    // finalize: one thread per boid
    if (tid < IBLK) {
        const int ib = blockIdx.x * IBLK + tid;

        const float Sx = red[0][tid][0];
        const float Sy = red[0][tid][1];
        const float Vx = red[0][tid][2];
        const float Vy = red[0][tid][3];
        const float Px = red[0][tid][4];
        const float Py = red[0][tid][5];
        const float C  = red[0][tid][6] - 1.0f;   // remove self

        const float2 vi = vel[ib];
        const float2 nz = noise[ib];

        // separation: normalize(-S)
        float nrm = sqrtf(Sx * Sx + Sy * Sy);
        float inv = 1.0f / fmaxf(nrm, EPSF);
        const float sepx = -Sx * inv;
        const float sepy = -Sy * inv;

        const float invC = 1.0f / C;

        // alignment: normalize((V - vi)/C - vi)
        const float avx = (Vx - vi.x) * invC - vi.x;
        const float avy = (Vy - vi.y) * invC - vi.y;
        nrm = sqrtf(avx * avx + avy * avy);
        inv = 1.0f / fmaxf(nrm, EPSF);
        const float alix = avx * inv;
        const float aliy = avy * inv;

        // cohesion: normalize(P/C)
        const float cx = Px * invC;
        const float cy = Py * invC;
        nrm = sqrtf(cx * cx + cy * cy);
        inv = 1.0f / fmaxf(nrm, EPSF);
        const float cohx = cx * inv;
        const float cohy = cy * inv;

        const float ws = *w_sep;
        const float wa = *w_ali;
        const float wc = *w_coh;
        const float wn = *w_ns;

        float ax = ws * sepx + wa * alix + wc * cohx + wn * nz.x;
        float ay = ws * sepy + wa * aliy + wc * cohy + wn * nz.y;

        nrm = sqrtf(ax * ax + ay * ay);
        if (nrm > 1.0f) {
            const float s = 1.0f / fmaxf(nrm, EPSF);
            ax *= s;
            ay *= s;
        }

        out[ib] = make_float2(ax, ay);
    }
}

extern "C" void kernel_launch(void* const* d_in, const int* in_sizes, int n_in,
                              void* d_out, int out_size)
{
    const float2* pos   = (const float2*)d_in[0];
    const float2* vel   = (const float2*)d_in[1];
    const float2* noise = (const float2*)d_in[2];
    const float*  wsep  = (const float*)d_in[3];
    const float*  wali  = (const float*)d_in[4];
    const float*  wcoh  = (const float*)d_in[5];
    const float*  wns   = (const float*)d_in[6];
    float2* out = (float2*)d_out;

    boids_kernel<<<GRID, TPB>>>(pos, vel, noise, wsep, wali, wcoh, wns, out);
}

// round 3
// speedup vs baseline: 1.5687x; 1.1450x over previous
#include <cuda_runtime.h>

// BoidPolicy: all-pairs boids on a unit torus. N=8192, out acc [N,2] f32.
//
// 3-kernel pipeline (all graph-capturable, no allocations):
//   k0: transpose pos/vel into SoA __device__ arrays
//   k1: main O(N^2) pass, packed f32x2 over j-pairs, branchless masks,
//       warp-tiles of (32 i x 256 j); partial sums -> global scratch
//   k2: reduce 32 chunk-partials per boid + epilogue (normalize/weights/clip)

#define NB      8192
#define TPB     256
#define JCHUNK  256                 // j per warp-tile
#define NCHUNK  (NB / JCHUNK)       // 32
#define NIGRP   (NB / 32)           // 256 i-groups of 32
#define NTILES  (NIGRP * NCHUNK)    // 8192 warp tiles
#define GRID1   (NTILES / 8)        // 1024 blocks, 8 warps each

#define SEP2F   4e-4f
#define PERC2F  0.04f
#define EPSF    1e-8f
#define MAGIC   12582912.0f         // 1.5 * 2^23

typedef unsigned long long u64;

__device__ float g_posx[NB];
__device__ float g_posy[NB];
__device__ float g_velx[NB];
__device__ float g_vely[NB];
__device__ float g_part[7 * NCHUNK * NB];   // [comp][chunk][boid]

__device__ __forceinline__ u64 pack2(float lo, float hi) {
    u64 r; asm("mov.b64 %0,{%1,%2};" : "=l"(r) : "f"(lo), "f"(hi)); return r;
}
__device__ __forceinline__ void unpack2(u64 v, float& lo, float& hi) {
    asm("mov.b64 {%0,%1},%2;" : "=f"(lo), "=f"(hi) : "l"(v));
}
__device__ __forceinline__ u64 f2add(u64 a, u64 b) {
    u64 d; asm("add.rn.f32x2 %0,%1,%2;" : "=l"(d) : "l"(a), "l"(b)); return d;
}
__device__ __forceinline__ u64 f2mul(u64 a, u64 b) {
    u64 d; asm("mul.rn.f32x2 %0,%1,%2;" : "=l"(d) : "l"(a), "l"(b)); return d;
}
__device__ __forceinline__ u64 f2fma(u64 a, u64 b, u64 c) {
    u64 d; asm("fma.rn.f32x2 %0,%1,%2,%3;" : "=l"(d) : "l"(a), "l"(b), "l"(c)); return d;
}
// mask = (t >= 0 per half) ? 1.0 : 0.0, exact (copysign(0.5,t)+0.5)
__device__ __forceinline__ u64 f2mask(u64 t, u64 half2) {
    u64 s = (t & 0x8000000080000000ULL) | 0x3F0000003F000000ULL;  // 2x LOP3
    return f2add(s, half2);
}

// ---------------- k0: AoS -> SoA transpose ----------------
__global__ void k0_transpose(const float2* __restrict__ pos,
                             const float2* __restrict__ vel)
{
    const int i = blockIdx.x * blockDim.x + threadIdx.x;
    const float2 p = pos[i];
    const float2 v = vel[i];
    g_posx[i] = p.x;  g_posy[i] = p.y;
    g_velx[i] = v.x;  g_vely[i] = v.y;
}

// ---------------- k1: main O(N^2) pass ----------------
__global__ __launch_bounds__(TPB)
void k1_pairs()
{
    const int lane = threadIdx.x & 31;
    const int w    = threadIdx.x >> 5;
    const int tile = blockIdx.x * 8 + w;
    const int g    = tile >> 5;          // i-group 0..255
    const int c    = tile & 31;          // j-chunk 0..31
    const int i    = g * 32 + lane;
    const int j0   = c * JCHUNK;

    const float pix = g_posx[i];
    const float piy = g_posy[i];

    const u64 nxi2   = pack2(-pix, -pix);
    const u64 nyi2   = pack2(-piy, -piy);
    const u64 C2     = pack2( MAGIC,  MAGIC);
    const u64 nC2    = pack2(-MAGIC, -MAGIC);
    const u64 nOne2  = pack2(-1.0f, -1.0f);
    const u64 half2  = pack2(0.5f, 0.5f);
    const u64 sep2c  = pack2(SEP2F, SEP2F);
    const u64 perc2c = pack2(PERC2F, PERC2F);

    u64 Sx2 = 0, Sy2 = 0, Px2 = 0, Py2 = 0, Vx2 = 0, Vy2 = 0, Cn2 = 0;

    const u64* __restrict__ ppx = (const u64*)(g_posx + j0);
    const u64* __restrict__ ppy = (const u64*)(g_posy + j0);
    const u64* __restrict__ pvx = (const u64*)(g_velx + j0);
    const u64* __restrict__ pvy = (const u64*)(g_vely + j0);

    #pragma unroll 8
    for (int jj = 0; jj < JCHUNK / 2; ++jj) {
        const u64 px2 = ppx[jj];          // warp-uniform -> broadcast
        const u64 py2 = ppy[jj];
        const u64 vx2 = pvx[jj];
        const u64 vy2 = pvy[jj];

        // toroidal wrapped diff via magic-constant rint
        const u64 dx2 = f2add(px2, nxi2);
        const u64 ux  = f2add(dx2, C2);
        const u64 rx  = f2add(ux, nC2);        // = rint(dx), exact
        const u64 dwx = f2fma(rx, nOne2, dx2); // dx - rint(dx)

        const u64 dy2 = f2add(py2, nyi2);
        const u64 uy  = f2add(dy2, C2);
        const u64 ry  = f2add(uy, nC2);
        const u64 dwy = f2fma(ry, nOne2, dy2);

        const u64 d2  = f2fma(dwy, dwy, f2mul(dwx, dwx));

        const u64 ms  = f2mask(f2fma(d2, nOne2, sep2c),  half2);
        const u64 mp  = f2mask(f2fma(d2, nOne2, perc2c), half2);

        Sx2 = f2fma(dwx, ms, Sx2);
        Sy2 = f2fma(dwy, ms, Sy2);
        Px2 = f2fma(dwx, mp, Px2);
        Py2 = f2fma(dwy, mp, Py2);
        Vx2 = f2fma(vx2, mp, Vx2);
        Vy2 = f2fma(vy2, mp, Vy2);
        Cn2 = f2add(Cn2, mp);
    }

    float a, b;
    float* base = g_part + (size_t)c * NB + i;   // [comp][chunk][boid], coalesced over lane
    unpack2(Sx2, a, b);  base[0 * NCHUNK * NB] = a + b;
    unpack2(Sy2, a, b);  base[1 * NCHUNK * NB] = a + b;
    unpack2(Px2, a, b);  base[2 * NCHUNK * NB] = a + b;
    unpack2(Py2, a, b);  base[3 * NCHUNK * NB] = a + b;
    unpack2(Vx2, a, b);  base[4 * NCHUNK * NB] = a + b;
    unpack2(Vy2, a, b);  base[5 * NCHUNK * NB] = a + b;
    unpack2(Cn2, a, b);  base[6 * NCHUNK * NB] = a + b;
}

// ---------------- k2: reduce + epilogue ----------------
__global__ void k2_finalize(const float2* __restrict__ vel,
                            const float2* __restrict__ noise,
                            const float*  __restrict__ w_sep,
                            const float*  __restrict__ w_ali,
                            const float*  __restrict__ w_coh,
                            const float*  __restrict__ w_ns,
                            float2*       __restrict__ out)
{
    const int i = blockIdx.x * blockDim.x + threadIdx.x;

    float s[7];
    #pragma unroll
    for (int comp = 0; comp < 7; ++comp) {
        const float* p = g_part + (size_t)comp * NCHUNK * NB + i;
        float acc = 0.0f;
        #pragma unroll
        for (int ch = 0; ch < NCHUNK; ++ch) acc += p[(size_t)ch * NB];
        s[comp] = acc;
    }

    const float Sx = s[0], Sy = s[1], Px = s[2], Py = s[3];
    const float Vx = s[4], Vy = s[5];
    const float C  = s[6] - 1.0f;               // remove self

    const float2 vi = vel[i];
    const float2 nz = noise[i];

    float nrm = sqrtf(Sx * Sx + Sy * Sy);
    float inv = 1.0f / fmaxf(nrm, EPSF);
    const float sepx = -Sx * inv;
    const float sepy = -Sy * inv;

    const float invC = 1.0f / C;

    const float avx = (Vx - vi.x) * invC - vi.x;
    const float avy = (Vy - vi.y) * invC - vi.y;
    nrm = sqrtf(avx * avx + avy * avy);
    inv = 1.0f / fmaxf(nrm, EPSF);
    const float alix = avx * inv;
    const float aliy = avy * inv;

    const float cx = Px * invC;
    const float cy = Py * invC;
    nrm = sqrtf(cx * cx + cy * cy);
    inv = 1.0f / fmaxf(nrm, EPSF);
    const float cohx = cx * inv;
    const float cohy = cy * inv;

    const float ws = *w_sep;
    const float wa = *w_ali;
    const float wc = *w_coh;
    const float wn = *w_ns;

    float ax = ws * sepx + wa * alix + wc * cohx + wn * nz.x;
    float ay = ws * sepy + wa * aliy + wc * cohy + wn * nz.y;

    nrm = sqrtf(ax * ax + ay * ay);
    if (nrm > 1.0f) {
        const float sc = 1.0f / fmaxf(nrm, EPSF);
        ax *= sc;
        ay *= sc;
    }

    out[i] = make_float2(ax, ay);
}

extern "C" void kernel_launch(void* const* d_in, const int* in_sizes, int n_in,
                              void* d_out, int out_size)
{
    const float2* pos   = (const float2*)d_in[0];
    const float2* vel   = (const float2*)d_in[1];
    const float2* noise = (const float2*)d_in[2];
    const float*  wsep  = (const float*)d_in[3];
    const float*  wali  = (const float*)d_in[4];
    const float*  wcoh  = (const float*)d_in[5];
    const float*  wns   = (const float*)d_in[6];
    float2* out = (float2*)d_out;

    k0_transpose<<<NB / TPB, TPB>>>(pos, vel);
    k1_pairs<<<GRID1, TPB>>>();
    k2_finalize<<<NB / TPB, TPB>>>(vel, noise, wsep, wali, wcoh, wns, out);
}